// round 2
// baseline (speedup 1.0000x reference)
#include <cuda_runtime.h>
#include <math.h>

#define BB 16
#define NN 4096
#define DD 64
#define KK 8
#define HH 4
#define EPSF 1e-5f
// 16 * (-0.5 * 64 * ln(2*pi))
#define LOGPI_SUM (-940.99305800158484f)

// ---------------- scratch (static device memory) ---------------------------
__device__ float g_x[BB * NN * DD];                    // LN'd embeddings
__device__ float g_keys[(size_t)BB * NN * KK * DD];    // [b][n][k][d]
__device__ float g_slots[BB * KK * DD];
__device__ float g_sigma[BB * KK * DD];
__device__ float g_mix[BB * KK];
__device__ float g_a[BB * KK * DD];     // -0.5/(sigma^2+eps)
__device__ float g_bq[BB * KK * DD];    // q/(sigma^2+eps)
__device__ float g_C[BB * KK * HH];     // logit bias per (b,k,h)
__device__ float g_A[BB * KK * HH];     // sum attn
__device__ float g_S2[BB * KK * DD];    // sum attn*k^2
__device__ float g_T[BB * KK * HH * DD];// sum attn*x  [b][k][h][e]

// ---------------- init ------------------------------------------------------
__global__ void k_init(const float* __restrict__ mu, const float* __restrict__ ls,
                       const float* __restrict__ mix0, const float* __restrict__ noise) {
    int i = blockIdx.x * 256 + threadIdx.x;
    if (i >= BB * KK * DD) return;
    int kd = i & (KK * DD - 1);
    float sg = expf(ls[kd]);
    g_sigma[i] = sg;
    g_slots[i] = mu[kd] + sg * noise[i];
    if ((i & 63) == 0) g_mix[i >> 6] = mix0[(i >> 6) & (KK - 1)];
}

// ---------------- LayerNorm of embeddings (warp per row) -------------------
__global__ void k_ln(const float* __restrict__ emb, const float* __restrict__ g,
                     const float* __restrict__ bt) {
    int row = blockIdx.x * 8 + (threadIdx.x >> 5);
    int lane = threadIdx.x & 31;
    float2 v = ((const float2*)emb)[(size_t)row * 32 + lane];
    float s = v.x + v.y, q = v.x * v.x + v.y * v.y;
#pragma unroll
    for (int o = 16; o; o >>= 1) {
        s += __shfl_xor_sync(0xffffffffu, s, o);
        q += __shfl_xor_sync(0xffffffffu, q, o);
    }
    float m = s * (1.f / 64.f);
    float var = q * (1.f / 64.f) - m * m;
    float r = rsqrtf(var + EPSF);
    float2 o;
    o.x = (v.x - m) * r * g[2 * lane] + bt[2 * lane];
    o.y = (v.y - m) * r * g[2 * lane + 1] + bt[2 * lane + 1];
    ((float2*)g_x)[(size_t)row * 32 + lane] = o;
}

// ---------------- keys GEMM: keys[b,n,k,:] = x[b,n,:] @ to_keys[k] ---------
__global__ __launch_bounds__(256) void k_keys(const float* __restrict__ tk) {
    __shared__ float xs[64 * 128];   // transposed: xs[e*128 + n]
    __shared__ float ws[64 * 64];    // ws[e*64 + d]
    int b = blockIdx.x >> 5;
    int n0 = (blockIdx.x & 31) << 7;
    int t = threadIdx.x;
    // fill x transposed: n = idx&127, e = idx>>7 (conflict-free stores)
    for (int idx = t; idx < 8192; idx += 256) {
        int n = idx & 127, e = idx >> 7;
        xs[e * 128 + n] = g_x[((size_t)b * NN + n0 + n) * 64 + e];
    }
    int tx = t & 7, ty = t >> 3;
    int d0 = tx << 3;     // 0..56
    int nr = ty << 2;     // 0..124
    for (int k = 0; k < KK; k++) {
        __syncthreads();
        for (int idx = t; idx < 1024; idx += 256)
            ((float4*)ws)[idx] = ((const float4*)tk)[(size_t)k * 1024 + idx];
        __syncthreads();
        float4 a0 = {0,0,0,0}, a1 = {0,0,0,0}, a2 = {0,0,0,0}, a3 = {0,0,0,0};
        float4 b0 = {0,0,0,0}, b1 = {0,0,0,0}, b2 = {0,0,0,0}, b3 = {0,0,0,0};
#pragma unroll 8
        for (int e = 0; e < 64; e++) {
            float4 w0 = *(const float4*)&ws[e * 64 + d0];
            float4 w1 = *(const float4*)&ws[e * 64 + d0 + 4];
            float4 xv = *(const float4*)&xs[e * 128 + nr];
            a0.x = fmaf(xv.x, w0.x, a0.x); a0.y = fmaf(xv.x, w0.y, a0.y);
            a0.z = fmaf(xv.x, w0.z, a0.z); a0.w = fmaf(xv.x, w0.w, a0.w);
            b0.x = fmaf(xv.x, w1.x, b0.x); b0.y = fmaf(xv.x, w1.y, b0.y);
            b0.z = fmaf(xv.x, w1.z, b0.z); b0.w = fmaf(xv.x, w1.w, b0.w);
            a1.x = fmaf(xv.y, w0.x, a1.x); a1.y = fmaf(xv.y, w0.y, a1.y);
            a1.z = fmaf(xv.y, w0.z, a1.z); a1.w = fmaf(xv.y, w0.w, a1.w);
            b1.x = fmaf(xv.y, w1.x, b1.x); b1.y = fmaf(xv.y, w1.y, b1.y);
            b1.z = fmaf(xv.y, w1.z, b1.z); b1.w = fmaf(xv.y, w1.w, b1.w);
            a2.x = fmaf(xv.z, w0.x, a2.x); a2.y = fmaf(xv.z, w0.y, a2.y);
            a2.z = fmaf(xv.z, w0.z, a2.z); a2.w = fmaf(xv.z, w0.w, a2.w);
            b2.x = fmaf(xv.z, w1.x, b2.x); b2.y = fmaf(xv.z, w1.y, b2.y);
            b2.z = fmaf(xv.z, w1.z, b2.z); b2.w = fmaf(xv.z, w1.w, b2.w);
            a3.x = fmaf(xv.w, w0.x, a3.x); a3.y = fmaf(xv.w, w0.y, a3.y);
            a3.z = fmaf(xv.w, w0.z, a3.z); a3.w = fmaf(xv.w, w0.w, a3.w);
            b3.x = fmaf(xv.w, w1.x, b3.x); b3.y = fmaf(xv.w, w1.y, b3.y);
            b3.z = fmaf(xv.w, w1.z, b3.z); b3.w = fmaf(xv.w, w1.w, b3.w);
        }
        size_t o0 = (((size_t)b * NN + n0 + nr) * KK + k) * 64 + d0;
        *(float4*)&g_keys[o0]            = a0; *(float4*)&g_keys[o0 + 4]            = b0;
        *(float4*)&g_keys[o0 + 512]      = a1; *(float4*)&g_keys[o0 + 512 + 4]      = b1;
        *(float4*)&g_keys[o0 + 1024]     = a2; *(float4*)&g_keys[o0 + 1024 + 4]     = b2;
        *(float4*)&g_keys[o0 + 1536]     = a3; *(float4*)&g_keys[o0 + 1536 + 4]     = b3;
    }
}

// ---------------- per-iteration slot preprocessing --------------------------
__global__ void k_pre(const float* __restrict__ tq, const float* __restrict__ gsl,
                      const float* __restrict__ bsl) {
    int bk = blockIdx.x;
    int k = bk & (KK - 1);
    int d = threadIdx.x;
    __shared__ float sh[64];
    float s = g_slots[bk * 64 + d];
    sh[d] = s;
    __syncthreads();
    float m = 0.f, q = 0.f;
#pragma unroll
    for (int j = 0; j < 64; j++) { float v = sh[j]; m += v; q += v * v; }
    m *= (1.f / 64.f);
    float var = q * (1.f / 64.f) - m * m;
    float sln = (s - m) * rsqrtf(var + EPSF) * gsl[d] + bsl[d];
    float qd = sln * tq[((size_t)k * 64 + d) * 64 + d];   // diag of to_queries
    float sg = g_sigma[bk * 64 + d];
    float invden = 1.f / (sg * sg + EPSF);
    g_a[bk * 64 + d] = -0.5f * invden;
    g_bq[bk * 64 + d] = qd * invden;
    float cp = -logf(fmaxf(sg, EPSF)) - 0.5f * qd * qd * invden;
#pragma unroll
    for (int o = 1; o < 16; o <<= 1) cp += __shfl_xor_sync(0xffffffffu, cp, o);
    if ((d & 15) == 0) g_C[bk * 4 + (d >> 4)] = logf(g_mix[bk] + EPSF) + LOGPI_SUM + cp;
    g_S2[bk * 64 + d] = 0.f;
    if (d < 4) g_A[bk * 4 + d] = 0.f;
#pragma unroll
    for (int i = 0; i < 4; i++) g_T[bk * 256 + i * 64 + d] = 0.f;
}

// ---------------- fused attention pass --------------------------------------
__global__ __launch_bounds__(256) void k_pass(float* __restrict__ attn_out, int last) {
    __shared__ float4 xs[2048];      // 32 KB: x tile, then reduction scratch
    int b = blockIdx.x >> 5;
    int n0 = (blockIdx.x & 31) << 7;
    int t = threadIdx.x, w = t >> 5, lane = t & 31;
    int bk = b * KK + (lane >> 2);
    int h = lane & 3;
    float a[16], bq[16];
#pragma unroll
    for (int j = 0; j < 16; j++) {
        a[j]  = g_a[bk * 64 + h * 16 + j];
        bq[j] = g_bq[bk * 64 + h * 16 + j];
    }
    float C = g_C[bk * 4 + h];
    for (int i = t; i < 2048; i += 256)
        xs[i] = ((const float4*)g_x)[((size_t)b * NN + n0) * 16 + i];
    __syncthreads();

    float4 Tacc[16];
#pragma unroll
    for (int e = 0; e < 16; e++) Tacc[e] = make_float4(0.f, 0.f, 0.f, 0.f);
    float S2l[16];
#pragma unroll
    for (int j = 0; j < 16; j++) S2l[j] = 0.f;
    float Aacc = 0.f;
    float* aout = attn_out + (size_t)bk * NN * 4 + h;
    const float4* kbase = ((const float4*)g_keys) + ((size_t)b * NN + n0) * 128 + lane * 4;

    float4 q0, q1, q2, q3;
    { const float4* kp = kbase + (size_t)(w * 16) * 128; q0 = kp[0]; q1 = kp[1]; q2 = kp[2]; q3 = kp[3]; }
#pragma unroll 2
    for (int ni = 0; ni < 16; ni++) {
        int nl = w * 16 + ni;
        float kv[16] = {q0.x, q0.y, q0.z, q0.w, q1.x, q1.y, q1.z, q1.w,
                        q2.x, q2.y, q2.z, q2.w, q3.x, q3.y, q3.z, q3.w};
        if (ni < 15) {
            const float4* kp = kbase + (size_t)(nl + 1) * 128;
            q0 = kp[0]; q1 = kp[1]; q2 = kp[2]; q3 = kp[3];
        }
        float lg = C;
#pragma unroll
        for (int j = 0; j < 16; j++) lg = fmaf(kv[j], fmaf(kv[j], a[j], bq[j]), lg);
        float mm = lg;
        mm = fmaxf(mm, __shfl_xor_sync(0xffffffffu, mm, 4));
        mm = fmaxf(mm, __shfl_xor_sync(0xffffffffu, mm, 8));
        mm = fmaxf(mm, __shfl_xor_sync(0xffffffffu, mm, 16));
        float ex = __expf(lg - mm);
        float ss = ex;
        ss += __shfl_xor_sync(0xffffffffu, ss, 4);
        ss += __shfl_xor_sync(0xffffffffu, ss, 8);
        ss += __shfl_xor_sync(0xffffffffu, ss, 16);
        float attn = ex / ss + EPSF;
        if (last) aout[(size_t)(n0 + nl) * 4] = attn;
        Aacc += attn;
#pragma unroll
        for (int j = 0; j < 16; j++) S2l[j] = fmaf(attn * kv[j], kv[j], S2l[j]);
        const float4* xp = &xs[nl * 16];
#pragma unroll
        for (int e = 0; e < 16; e++) {
            float4 xv = xp[e];
            Tacc[e].x = fmaf(attn, xv.x, Tacc[e].x);
            Tacc[e].y = fmaf(attn, xv.y, Tacc[e].y);
            Tacc[e].z = fmaf(attn, xv.z, Tacc[e].z);
            Tacc[e].w = fmaf(attn, xv.w, Tacc[e].w);
        }
    }

    // ---- cross-warp tree reduction (reuse xs) ----
    __syncthreads();
    float4* red4 = (float4*)xs;
#define TIDX(ww, e) ((ww) * 512 + lane * 16 + (((e) + lane) & 15))
    if (w >= 4) {
#pragma unroll
        for (int e = 0; e < 16; e++) red4[TIDX(w - 4, e)] = Tacc[e];
    }
    __syncthreads();
    if (w < 4) {
#pragma unroll
        for (int e = 0; e < 16; e++) {
            float4 v = red4[TIDX(w, e)];
            Tacc[e].x += v.x; Tacc[e].y += v.y; Tacc[e].z += v.z; Tacc[e].w += v.w;
        }
    }
    __syncthreads();
    if (w == 2 || w == 3) {
#pragma unroll
        for (int e = 0; e < 16; e++) red4[TIDX(w - 2, e)] = Tacc[e];
    }
    __syncthreads();
    if (w < 2) {
#pragma unroll
        for (int e = 0; e < 16; e++) {
            float4 v = red4[TIDX(w, e)];
            Tacc[e].x += v.x; Tacc[e].y += v.y; Tacc[e].z += v.z; Tacc[e].w += v.w;
        }
    }
    __syncthreads();
    if (w == 1) {
#pragma unroll
        for (int e = 0; e < 16; e++) red4[TIDX(0, e)] = Tacc[e];
    }
    __syncthreads();
    if (w == 0) {
#pragma unroll
        for (int e = 0; e < 16; e++) {
            float4 v = red4[TIDX(0, e)];
            float* gp = &g_T[(size_t)b * 2048 + lane * 64 + e * 4];
            atomicAdd(gp + 0, Tacc[e].x + v.x);
            atomicAdd(gp + 1, Tacc[e].y + v.y);
            atomicAdd(gp + 2, Tacc[e].z + v.z);
            atomicAdd(gp + 3, Tacc[e].w + v.w);
        }
    }
    // ---- S2 + A tree ----
    __syncthreads();
    float* redf = (float*)xs;
#define SIDX(ww, j) ((ww) * 544 + lane * 17 + (j))
    if (w >= 4) {
#pragma unroll
        for (int j = 0; j < 16; j++) redf[SIDX(w - 4, j)] = S2l[j];
        redf[SIDX(w - 4, 16)] = Aacc;
    }
    __syncthreads();
    if (w < 4) {
#pragma unroll
        for (int j = 0; j < 16; j++) S2l[j] += redf[SIDX(w, j)];
        Aacc += redf[SIDX(w, 16)];
    }
    __syncthreads();
    if (w == 2 || w == 3) {
#pragma unroll
        for (int j = 0; j < 16; j++) redf[SIDX(w - 2, j)] = S2l[j];
        redf[SIDX(w - 2, 16)] = Aacc;
    }
    __syncthreads();
    if (w < 2) {
#pragma unroll
        for (int j = 0; j < 16; j++) S2l[j] += redf[SIDX(w, j)];
        Aacc += redf[SIDX(w, 16)];
    }
    __syncthreads();
    if (w == 1) {
#pragma unroll
        for (int j = 0; j < 16; j++) redf[SIDX(0, j)] = S2l[j];
        redf[SIDX(0, 16)] = Aacc;
    }
    __syncthreads();
    if (w == 0) {
#pragma unroll
        for (int j = 0; j < 16; j++)
            atomicAdd(&g_S2[(size_t)b * 512 + lane * 16 + j], S2l[j] + redf[SIDX(0, j)]);
        atomicAdd(&g_A[b * 32 + lane], Aacc + redf[SIDX(0, 16)]);
    }
}

// ---------------- slot update: upd/sigma/mixing + GRU + FF ------------------
__global__ void k_upd(const float* __restrict__ tk, const float* __restrict__ tv,
                      const float* __restrict__ wih, const float* __restrict__ whh,
                      const float* __restrict__ bih, const float* __restrict__ bhh,
                      const float* __restrict__ w1, const float* __restrict__ b1,
                      const float* __restrict__ w2, const float* __restrict__ b2,
                      const float* __restrict__ gff, const float* __restrict__ bff,
                      const float* __restrict__ noisef, float* __restrict__ out_slots,
                      int last) {
    int bk = blockIdx.x;
    int k = bk & (KK - 1);
    int d = threadIdx.x;
    int h = d >> 4;
    __shared__ float Tsh[4][64];
    __shared__ float Ash[4];
    __shared__ float ush[64], hsh[64], presh[64], h1sh[256], sh[64];
#pragma unroll
    for (int i = 0; i < 4; i++) Tsh[i][d] = g_T[bk * 256 + i * 64 + d];
    if (d < 4) Ash[d] = g_A[bk * 4 + d];
    __syncthreads();
    float Nk = Ash[0] + Ash[1] + Ash[2] + Ash[3];
    float u = 0.f, s1 = 0.f;
#pragma unroll 8
    for (int e = 0; e < 64; e++) {
        float tvv = Tsh[h][e];
        u  = fmaf(tvv, tv[((size_t)k * 64 + e) * 64 + d], u);
        s1 = fmaf(tvv, tk[((size_t)k * 64 + e) * 64 + d], s1);
    }
    float invNk = 1.f / Nk;
    u *= (invNk + EPSF);                       // upd (scaled) == nq
    float sig2 = fmaxf(g_S2[bk * 64 + d] - 2.f * u * s1 + u * u * Ash[h], 0.f);
    float sigma = sqrtf(sig2 * invNk) + EPSF;
    g_sigma[bk * 64 + d] = sigma;
    if (d == 0) g_mix[bk] = Nk * (1.f / (float)NN);
    float hprev = g_slots[bk * 64 + d];
    ush[d] = u;
    hsh[d] = hprev;
    __syncthreads();
    float xr = bih[d], xz = bih[64 + d], xn = bih[128 + d];
    float hr = bhh[d], hz = bhh[64 + d], hn = bhh[128 + d];
#pragma unroll 8
    for (int e = 0; e < 64; e++) {
        float ue = ush[e], he = hsh[e];
        xr = fmaf(ue, wih[d * 64 + e], xr);
        xz = fmaf(ue, wih[(64 + d) * 64 + e], xz);
        xn = fmaf(ue, wih[(128 + d) * 64 + e], xn);
        hr = fmaf(he, whh[d * 64 + e], hr);
        hz = fmaf(he, whh[(64 + d) * 64 + e], hz);
        hn = fmaf(he, whh[(128 + d) * 64 + e], hn);
    }
    float r = 1.f / (1.f + expf(-(xr + hr)));
    float z = 1.f / (1.f + expf(-(xz + hz)));
    float nn2 = tanhf(xn + r * hn);
    float snew = (1.f - z) * nn2 + z * hprev;
    sh[d] = snew;
    __syncthreads();
    float m = 0.f, qq = 0.f;
#pragma unroll
    for (int j = 0; j < 64; j++) { float v = sh[j]; m += v; qq += v * v; }
    m *= (1.f / 64.f);
    float var = qq * (1.f / 64.f) - m * m;
    float pre = (snew - m) * rsqrtf(var + EPSF) * gff[d] + bff[d];
    presh[d] = pre;
    __syncthreads();
    for (int j = d; j < 256; j += 64) {
        float acc = b1[j];
#pragma unroll 8
        for (int e = 0; e < 64; e++) acc = fmaf(presh[e], w1[(size_t)j * 64 + e], acc);
        h1sh[j] = fmaxf(acc, 0.f);
    }
    __syncthreads();
    float o = snew + b2[d];
#pragma unroll 8
    for (int j = 0; j < 256; j++) o = fmaf(h1sh[j], w2[(size_t)d * 256 + j], o);
    g_slots[bk * 64 + d] = o;
    if (last) out_slots[bk * 64 + d] = o + sigma * noisef[bk * 64 + d];
}

// ---------------- launch ----------------------------------------------------
extern "C" void kernel_launch(void* const* d_in, const int* in_sizes, int n_in,
                              void* d_out, int out_size) {
    const float* emb   = (const float*)d_in[0];
    const float* mu    = (const float*)d_in[1];
    const float* ls    = (const float*)d_in[2];
    const float* mix0  = (const float*)d_in[3];
    const float* tk    = (const float*)d_in[4];
    const float* tq    = (const float*)d_in[5];
    const float* tv    = (const float*)d_in[6];
    const float* wih   = (const float*)d_in[7];
    const float* whh   = (const float*)d_in[8];
    const float* bih   = (const float*)d_in[9];
    const float* bhh   = (const float*)d_in[10];
    const float* w1    = (const float*)d_in[11];
    const float* b1    = (const float*)d_in[12];
    const float* w2    = (const float*)d_in[13];
    const float* b2    = (const float*)d_in[14];
    const float* ling  = (const float*)d_in[15];
    const float* linb  = (const float*)d_in[16];
    const float* lslg  = (const float*)d_in[17];
    const float* lslb  = (const float*)d_in[18];
    const float* lffg  = (const float*)d_in[19];
    const float* lffb  = (const float*)d_in[20];
    const float* nzi   = (const float*)d_in[21];
    const float* nzf   = (const float*)d_in[22];

    float* out_slots = (float*)d_out;                  // [B,K,D] = 8192 floats
    float* out_attn  = (float*)d_out + BB * KK * DD;   // [B,K,N,H]

    k_init<<<(BB * KK * DD + 255) / 256, 256>>>(mu, ls, mix0, nzi);
    k_ln<<<BB * NN / 8, 256>>>(emb, ling, linb);
    k_keys<<<BB * 32, 256>>>(tk);
    for (int it = 0; it < 3; it++) {
        int last = (it == 2);
        k_pre<<<BB * KK, 64>>>(tq, lslg, lslb);
        k_pass<<<BB * 32, 256>>>(out_attn, last);
        k_upd<<<BB * KK, 64>>>(tk, tv, wih, whh, bih, bhh, w1, b1, w2, b2,
                               lffg, lffb, nzf, out_slots, last);
    }
}

// round 3
// speedup vs baseline: 1.2212x; 1.2212x over previous
#include <cuda_runtime.h>
#include <math.h>

#define BB 16
#define NN 4096
#define DD 64
#define KK 8
#define HH 4
#define EPSF 1e-5f
// 16 * (-0.5 * 64 * ln(2*pi))
#define LOGPI_SUM (-940.99305800158484f)

typedef unsigned long long ull;

// ---------------- packed f32x2 helpers --------------------------------------
__device__ __forceinline__ ull pk2(float x, float y) {
    ull r; asm("mov.b64 %0, {%1, %2};" : "=l"(r) : "f"(x), "f"(y)); return r;
}
__device__ __forceinline__ void fma2(ull& d, ull a, ull b) {
    asm("fma.rn.f32x2 %0, %1, %2, %0;" : "+l"(d) : "l"(a), "l"(b));
}
__device__ __forceinline__ ull fma2r(ull a, ull b, ull c) {
    ull d; asm("fma.rn.f32x2 %0, %1, %2, %3;" : "=l"(d) : "l"(a), "l"(b), "l"(c)); return d;
}
__device__ __forceinline__ ull mul2(ull a, ull b) {
    ull d; asm("mul.rn.f32x2 %0, %1, %2;" : "=l"(d) : "l"(a), "l"(b)); return d;
}
union F4U { float4 v; ull u[2]; float s[4]; };

// ---------------- scratch (static device memory) ---------------------------
__device__ float g_x[BB * NN * DD];
__device__ float g_keys[(size_t)BB * NN * KK * DD];    // [b][n][k][d]
__device__ float g_slots[BB * KK * DD];
__device__ float g_sigma[BB * KK * DD];
__device__ float g_a[BB * KK * DD];     // -0.5/(sigma^2+eps)
__device__ float g_bq[BB * KK * DD];    // q/(sigma^2+eps)
__device__ float g_C[BB * KK * HH];     // logit bias per (b,k,h)
__device__ float g_A[BB * KK * HH];     // sum attn
__device__ float g_S2[BB * KK * DD];    // sum attn*k^2
__device__ float g_T[BB * KK * HH * DD];// sum attn*x  [b][k][h][e]

// ---------------- init + first-iteration coefficients ----------------------
__global__ void k_init_pre(const float* __restrict__ mu, const float* __restrict__ ls,
                           const float* __restrict__ mix0, const float* __restrict__ noise,
                           const float* __restrict__ tq, const float* __restrict__ gsl,
                           const float* __restrict__ bsl) {
    int bk = blockIdx.x, k = bk & (KK - 1);
    int d = threadIdx.x, h = d >> 4;
    __shared__ float sh[64];
    float sg = expf(ls[k * 64 + d]);
    float slot = mu[k * 64 + d] + sg * noise[bk * 64 + d];
    g_sigma[bk * 64 + d] = sg;
    g_slots[bk * 64 + d] = slot;
    sh[d] = slot;
    __syncthreads();
    float m = 0.f, q = 0.f;
#pragma unroll
    for (int j = 0; j < 64; j++) { float v = sh[j]; m += v; q += v * v; }
    m *= (1.f / 64.f);
    float var = q * (1.f / 64.f) - m * m;
    float sln = (slot - m) * rsqrtf(var + EPSF) * gsl[d] + bsl[d];
    float qd = sln * tq[((size_t)k * 64 + d) * 64 + d];
    float invden = 1.f / (sg * sg + EPSF);
    g_a[bk * 64 + d] = -0.5f * invden;
    g_bq[bk * 64 + d] = qd * invden;
    float cp = -logf(fmaxf(sg, EPSF)) - 0.5f * qd * qd * invden;
#pragma unroll
    for (int o = 1; o < 16; o <<= 1) cp += __shfl_xor_sync(0xffffffffu, cp, o);
    if ((d & 15) == 0) g_C[bk * 4 + h] = logf(mix0[k] + EPSF) + LOGPI_SUM + cp;
    g_S2[bk * 64 + d] = 0.f;
    if (d < 4) g_A[bk * 4 + d] = 0.f;
#pragma unroll
    for (int i = 0; i < 4; i++) g_T[bk * 256 + i * 64 + d] = 0.f;
}

// ---------------- LayerNorm of embeddings (warp per row) -------------------
__global__ void k_ln(const float* __restrict__ emb, const float* __restrict__ g,
                     const float* __restrict__ bt) {
    int row = blockIdx.x * 8 + (threadIdx.x >> 5);
    int lane = threadIdx.x & 31;
    float2 v = ((const float2*)emb)[(size_t)row * 32 + lane];
    float s = v.x + v.y, q = v.x * v.x + v.y * v.y;
#pragma unroll
    for (int o = 16; o; o >>= 1) {
        s += __shfl_xor_sync(0xffffffffu, s, o);
        q += __shfl_xor_sync(0xffffffffu, q, o);
    }
    float m = s * (1.f / 64.f);
    float var = q * (1.f / 64.f) - m * m;
    float r = rsqrtf(var + EPSF);
    float2 o;
    o.x = (v.x - m) * r * g[2 * lane] + bt[2 * lane];
    o.y = (v.y - m) * r * g[2 * lane + 1] + bt[2 * lane + 1];
    ((float2*)g_x)[(size_t)row * 32 + lane] = o;
}

// ---------------- keys GEMM with packed f32x2 FMA ---------------------------
__global__ __launch_bounds__(256) void k_keys(const float* __restrict__ tk) {
    __shared__ float xs[64 * 128];   // transposed: xs[e*128 + n]
    __shared__ float ws[64 * 64];    // ws[e*64 + d]
    int b = blockIdx.x >> 5;
    int n0 = (blockIdx.x & 31) << 7;
    int t = threadIdx.x;
    for (int idx = t; idx < 8192; idx += 256) {
        int n = idx & 127, e = idx >> 7;
        xs[e * 128 + n] = g_x[((size_t)b * NN + n0 + n) * 64 + e];
    }
    int tx = t & 7, ty = t >> 3;
    int d0 = tx << 3;     // 0..56
    int nr = ty << 2;     // 0..124
    for (int k = 0; k < KK; k++) {
        __syncthreads();
        for (int idx = t; idx < 1024; idx += 256)
            ((float4*)ws)[idx] = ((const float4*)tk)[(size_t)k * 1024 + idx];
        __syncthreads();
        ull acc[4][4];
#pragma unroll
        for (int n = 0; n < 4; n++)
#pragma unroll
            for (int p = 0; p < 4; p++) acc[n][p] = 0ull;
#pragma unroll 8
        for (int e = 0; e < 64; e++) {
            F4U w0; w0.v = *(const float4*)&ws[e * 64 + d0];
            F4U w1; w1.v = *(const float4*)&ws[e * 64 + d0 + 4];
            F4U xv; xv.v = *(const float4*)&xs[e * 128 + nr];
            ull xb0 = pk2(xv.s[0], xv.s[0]);
            ull xb1 = pk2(xv.s[1], xv.s[1]);
            ull xb2 = pk2(xv.s[2], xv.s[2]);
            ull xb3 = pk2(xv.s[3], xv.s[3]);
            fma2(acc[0][0], xb0, w0.u[0]); fma2(acc[0][1], xb0, w0.u[1]);
            fma2(acc[0][2], xb0, w1.u[0]); fma2(acc[0][3], xb0, w1.u[1]);
            fma2(acc[1][0], xb1, w0.u[0]); fma2(acc[1][1], xb1, w0.u[1]);
            fma2(acc[1][2], xb1, w1.u[0]); fma2(acc[1][3], xb1, w1.u[1]);
            fma2(acc[2][0], xb2, w0.u[0]); fma2(acc[2][1], xb2, w0.u[1]);
            fma2(acc[2][2], xb2, w1.u[0]); fma2(acc[2][3], xb2, w1.u[1]);
            fma2(acc[3][0], xb3, w0.u[0]); fma2(acc[3][1], xb3, w0.u[1]);
            fma2(acc[3][2], xb3, w1.u[0]); fma2(acc[3][3], xb3, w1.u[1]);
        }
        size_t o0 = (((size_t)b * NN + n0 + nr) * KK + k) * 64 + d0;
#pragma unroll
        for (int n = 0; n < 4; n++) {
            F4U oa, ob;
            oa.u[0] = acc[n][0]; oa.u[1] = acc[n][1];
            ob.u[0] = acc[n][2]; ob.u[1] = acc[n][3];
            *(float4*)&g_keys[o0 + (size_t)n * 512]     = oa.v;
            *(float4*)&g_keys[o0 + (size_t)n * 512 + 4] = ob.v;
        }
    }
}

// ---------------- fused attention pass (packed math) ------------------------
__global__ __launch_bounds__(256) void k_pass(float* __restrict__ attn_out, int last) {
    __shared__ float4 xs[2048];      // 32 KB: x tile, then reduction scratch
    int b = blockIdx.x >> 5;
    int n0 = (blockIdx.x & 31) << 7;
    int t = threadIdx.x, w = t >> 5, lane = t & 31;
    int bk = b * KK + (lane >> 2);
    int h = lane & 3;
    F4U a4[4], b4[4];
#pragma unroll
    for (int i = 0; i < 4; i++) {
        a4[i].v = *(const float4*)&g_a[bk * 64 + h * 16 + i * 4];
        b4[i].v = *(const float4*)&g_bq[bk * 64 + h * 16 + i * 4];
    }
    float C = g_C[bk * 4 + h];
    for (int i = t; i < 2048; i += 256)
        xs[i] = ((const float4*)g_x)[((size_t)b * NN + n0) * 16 + i];
    __syncthreads();

    F4U Tacc[16];
#pragma unroll
    for (int e = 0; e < 16; e++) { Tacc[e].u[0] = 0ull; Tacc[e].u[1] = 0ull; }
    F4U S2a[4];
#pragma unroll
    for (int j = 0; j < 4; j++) { S2a[j].u[0] = 0ull; S2a[j].u[1] = 0ull; }
    float Aacc = 0.f;
    float* aout = attn_out + (size_t)bk * NN * 4 + h;
    const float4* kbase = ((const float4*)g_keys) + ((size_t)b * NN + n0) * 128 + lane * 4;

    F4U q0, q1, q2, q3;
    { const float4* kp = kbase + (size_t)(w * 16) * 128;
      q0.v = kp[0]; q1.v = kp[1]; q2.v = kp[2]; q3.v = kp[3]; }
#pragma unroll 2
    for (int ni = 0; ni < 16; ni++) {
        int nl = w * 16 + ni;
        ull kp8[8] = {q0.u[0], q0.u[1], q1.u[0], q1.u[1], q2.u[0], q2.u[1], q3.u[0], q3.u[1]};
        if (ni < 15) {
            const float4* kp = kbase + (size_t)(nl + 1) * 128;
            q0.v = kp[0]; q1.v = kp[1]; q2.v = kp[2]; q3.v = kp[3];
        }
        ull lgp = 0ull;
#pragma unroll
        for (int j = 0; j < 8; j++) {
            ull tmp = fma2r(kp8[j], a4[j >> 1].u[j & 1], b4[j >> 1].u[j & 1]);
            lgp = fma2r(kp8[j], tmp, lgp);
        }
        F4U lgu; lgu.u[0] = lgp;
        float lg = C + lgu.s[0] + lgu.s[1];
        float mm = lg;
        mm = fmaxf(mm, __shfl_xor_sync(0xffffffffu, mm, 4));
        mm = fmaxf(mm, __shfl_xor_sync(0xffffffffu, mm, 8));
        mm = fmaxf(mm, __shfl_xor_sync(0xffffffffu, mm, 16));
        float ex = __expf(lg - mm);
        float ss = ex;
        ss += __shfl_xor_sync(0xffffffffu, ss, 4);
        ss += __shfl_xor_sync(0xffffffffu, ss, 8);
        ss += __shfl_xor_sync(0xffffffffu, ss, 16);
        float attn = __fdividef(ex, ss) + EPSF;
        if (last) aout[(size_t)(n0 + nl) * 4] = attn;
        Aacc += attn;
        ull attn2 = pk2(attn, attn);
#pragma unroll
        for (int j = 0; j < 8; j++) {
            ull ak = mul2(attn2, kp8[j]);
            S2a[j >> 1].u[j & 1] = fma2r(ak, kp8[j], S2a[j >> 1].u[j & 1]);
        }
        const float4* xp = &xs[nl * 16];
#pragma unroll
        for (int e = 0; e < 16; e++) {
            F4U xv; xv.v = xp[e];
            Tacc[e].u[0] = fma2r(attn2, xv.u[0], Tacc[e].u[0]);
            Tacc[e].u[1] = fma2r(attn2, xv.u[1], Tacc[e].u[1]);
        }
    }

    // ---- cross-warp tree reduction (reuse xs) ----
    __syncthreads();
    float4* red4 = (float4*)xs;
#define TIDX(ww, e) ((ww) * 512 + lane * 16 + (((e) + lane) & 15))
    if (w >= 4) {
#pragma unroll
        for (int e = 0; e < 16; e++) red4[TIDX(w - 4, e)] = Tacc[e].v;
    }
    __syncthreads();
    if (w < 4) {
#pragma unroll
        for (int e = 0; e < 16; e++) {
            float4 v = red4[TIDX(w, e)];
            Tacc[e].v.x += v.x; Tacc[e].v.y += v.y; Tacc[e].v.z += v.z; Tacc[e].v.w += v.w;
        }
    }
    __syncthreads();
    if (w == 2 || w == 3) {
#pragma unroll
        for (int e = 0; e < 16; e++) red4[TIDX(w - 2, e)] = Tacc[e].v;
    }
    __syncthreads();
    if (w < 2) {
#pragma unroll
        for (int e = 0; e < 16; e++) {
            float4 v = red4[TIDX(w, e)];
            Tacc[e].v.x += v.x; Tacc[e].v.y += v.y; Tacc[e].v.z += v.z; Tacc[e].v.w += v.w;
        }
    }
    __syncthreads();
    if (w == 1) {
#pragma unroll
        for (int e = 0; e < 16; e++) red4[TIDX(0, e)] = Tacc[e].v;
    }
    __syncthreads();
    if (w == 0) {
#pragma unroll
        for (int e = 0; e < 16; e++) {
            float4 v = red4[TIDX(0, e)];
            float* gp = &g_T[(size_t)b * 2048 + lane * 64 + e * 4];
            atomicAdd(gp + 0, Tacc[e].v.x + v.x);
            atomicAdd(gp + 1, Tacc[e].v.y + v.y);
            atomicAdd(gp + 2, Tacc[e].v.z + v.z);
            atomicAdd(gp + 3, Tacc[e].v.w + v.w);
        }
    }
    // ---- S2 + A tree ----
    __syncthreads();
    float* redf = (float*)xs;
#define SIDX(ww, j) ((ww) * 544 + lane * 17 + (j))
    if (w >= 4) {
#pragma unroll
        for (int j = 0; j < 16; j++) redf[SIDX(w - 4, j)] = S2a[j >> 2].s[j & 3];
        redf[SIDX(w - 4, 16)] = Aacc;
    }
    __syncthreads();
    if (w < 4) {
#pragma unroll
        for (int j = 0; j < 16; j++) S2a[j >> 2].s[j & 3] += redf[SIDX(w, j)];
        Aacc += redf[SIDX(w, 16)];
    }
    __syncthreads();
    if (w == 2 || w == 3) {
#pragma unroll
        for (int j = 0; j < 16; j++) redf[SIDX(w - 2, j)] = S2a[j >> 2].s[j & 3];
        redf[SIDX(w - 2, 16)] = Aacc;
    }
    __syncthreads();
    if (w < 2) {
#pragma unroll
        for (int j = 0; j < 16; j++) S2a[j >> 2].s[j & 3] += redf[SIDX(w, j)];
        Aacc += redf[SIDX(w, 16)];
    }
    __syncthreads();
    if (w == 1) {
#pragma unroll
        for (int j = 0; j < 16; j++) redf[SIDX(0, j)] = S2a[j >> 2].s[j & 3];
        redf[SIDX(0, 16)] = Aacc;
    }
    __syncthreads();
    if (w == 0) {
#pragma unroll
        for (int j = 0; j < 16; j++)
            atomicAdd(&g_S2[(size_t)b * 512 + lane * 16 + j],
                      S2a[j >> 2].s[j & 3] + redf[SIDX(0, j)]);
        atomicAdd(&g_A[b * 32 + lane], Aacc + redf[SIDX(0, 16)]);
    }
}

// ---------------- slot update + fused next-iter pre (128 threads) ----------
__global__ __launch_bounds__(128) void k_upd(
        const float* __restrict__ tk, const float* __restrict__ tv,
        const float* __restrict__ wih, const float* __restrict__ whh,
        const float* __restrict__ bih, const float* __restrict__ bhh,
        const float* __restrict__ w1, const float* __restrict__ b1,
        const float* __restrict__ w2, const float* __restrict__ b2,
        const float* __restrict__ gff, const float* __restrict__ bff,
        const float* __restrict__ tq, const float* __restrict__ gsl,
        const float* __restrict__ bsl,
        const float* __restrict__ noisef, float* __restrict__ out_slots, int last) {
    int bk = blockIdx.x;
    int k = bk & (KK - 1);
    int t = threadIdx.x;
    int d = t & 63, half = t >> 6;
    int h = d >> 4;
    __shared__ float Tsh[4][64], Ash[4];
    __shared__ float pu[2][64], ps1[2][64];
    __shared__ float ush[64], hsh[64];
    __shared__ float gsh[6][64];
    __shared__ float sh[64], presh[64], h1sh[256], pw2[2][64], osh[64];
    for (int i = t; i < 256; i += 128) Tsh[i >> 6][i & 63] = g_T[bk * 256 + i];
    if (t < 4) Ash[t] = g_A[bk * 4 + t];
    if (t >= 64) hsh[d] = g_slots[bk * 64 + d];
    __syncthreads();
    float Nk = Ash[0] + Ash[1] + Ash[2] + Ash[3];
    // split-e partial dots for u (to_values) and s1 (to_keys)
    {
        float u = 0.f, s1 = 0.f;
        int e0 = half * 32;
#pragma unroll 8
        for (int e = e0; e < e0 + 32; e++) {
            float tvv = Tsh[h][e];
            u  = fmaf(tvv, tv[((size_t)k * 64 + e) * 64 + d], u);
            s1 = fmaf(tvv, tk[((size_t)k * 64 + e) * 64 + d], s1);
        }
        pu[half][d] = u; ps1[half][d] = s1;
    }
    __syncthreads();
    float sigma_d = 0.f, u = 0.f;
    if (t < 64) {
        u = pu[0][d] + pu[1][d];
        float s1 = ps1[0][d] + ps1[1][d];
        float invNk = 1.f / Nk;
        u *= (invNk + EPSF);                   // upd == nq
        float sig2 = fmaxf(g_S2[bk * 64 + d] - 2.f * u * s1 + u * u * Ash[h], 0.f);
        sigma_d = sqrtf(sig2 * invNk) + EPSF;
        g_sigma[bk * 64 + d] = sigma_d;
        ush[d] = u;
    }
    __syncthreads();
    // gates: half 0 -> x-gates from ush (wih), half 1 -> h-gates from hsh (whh)
    {
        const float* W  = half ? whh : wih;
        const float* bi = half ? bhh : bih;
        const float* vi = half ? hsh : ush;
        float g0 = bi[d], g1 = bi[64 + d], g2 = bi[128 + d];
#pragma unroll 8
        for (int e = 0; e < 64; e++) {
            float v = vi[e];
            g0 = fmaf(v, W[d * 64 + e], g0);
            g1 = fmaf(v, W[(64 + d) * 64 + e], g1);
            g2 = fmaf(v, W[(128 + d) * 64 + e], g2);
        }
        gsh[half * 3 + 0][d] = g0;
        gsh[half * 3 + 1][d] = g1;
        gsh[half * 3 + 2][d] = g2;
    }
    __syncthreads();
    float snew = 0.f;
    if (t < 64) {
        float r = 1.f / (1.f + expf(-(gsh[0][d] + gsh[3][d])));
        float z = 1.f / (1.f + expf(-(gsh[1][d] + gsh[4][d])));
        float nn2 = tanhf(gsh[2][d] + r * gsh[5][d]);
        snew = (1.f - z) * nn2 + z * hsh[d];
        sh[d] = snew;
    }
    __syncthreads();
    if (t < 64) {
        float m = 0.f, qq = 0.f;
#pragma unroll
        for (int j = 0; j < 64; j++) { float v = sh[j]; m += v; qq += v * v; }
        m *= (1.f / 64.f);
        float var = qq * (1.f / 64.f) - m * m;
        presh[d] = (snew - m) * rsqrtf(var + EPSF) * gff[d] + bff[d];
    }
    __syncthreads();
    for (int j = t; j < 256; j += 128) {
        float acc = b1[j];
#pragma unroll 8
        for (int e = 0; e < 64; e++) acc = fmaf(presh[e], w1[(size_t)j * 64 + e], acc);
        h1sh[j] = fmaxf(acc, 0.f);
    }
    __syncthreads();
    {
        float o = 0.f;
        int j0 = half * 128;
#pragma unroll 8
        for (int j = j0; j < j0 + 128; j++) o = fmaf(h1sh[j], w2[(size_t)d * 256 + j], o);
        pw2[half][d] = o;
    }
    __syncthreads();
    if (t < 64) {
        float o = sh[d] + b2[d] + pw2[0][d] + pw2[1][d];
        g_slots[bk * 64 + d] = o;
        if (last) out_slots[bk * 64 + d] = o + sigma_d * noisef[bk * 64 + d];
        osh[d] = o;
    }
    __syncthreads();
    if (!last) {
        if (t < 64) {
            float m = 0.f, qq = 0.f;
#pragma unroll
            for (int j = 0; j < 64; j++) { float v = osh[j]; m += v; qq += v * v; }
            m *= (1.f / 64.f);
            float var = qq * (1.f / 64.f) - m * m;
            float sln = (osh[d] - m) * rsqrtf(var + EPSF) * gsl[d] + bsl[d];
            float qd = sln * tq[((size_t)k * 64 + d) * 64 + d];
            float invden = 1.f / (sigma_d * sigma_d + EPSF);
            g_a[bk * 64 + d]  = -0.5f * invden;
            g_bq[bk * 64 + d] = qd * invden;
            float cp = -logf(fmaxf(sigma_d, EPSF)) - 0.5f * qd * qd * invden;
#pragma unroll
            for (int o = 1; o < 16; o <<= 1) cp += __shfl_xor_sync(0xffffffffu, cp, o);
            if ((d & 15) == 0)
                g_C[bk * 4 + h] = logf(Nk * (1.f / (float)NN) + EPSF) + LOGPI_SUM + cp;
            g_S2[bk * 64 + d] = 0.f;
            if (d < 4) g_A[bk * 4 + d] = 0.f;
        }
        for (int i = t; i < 256; i += 128) g_T[bk * 256 + i] = 0.f;
    }
}

// ---------------- launch ----------------------------------------------------
extern "C" void kernel_launch(void* const* d_in, const int* in_sizes, int n_in,
                              void* d_out, int out_size) {
    const float* emb   = (const float*)d_in[0];
    const float* mu    = (const float*)d_in[1];
    const float* ls    = (const float*)d_in[2];
    const float* mix0  = (const float*)d_in[3];
    const float* tk    = (const float*)d_in[4];
    const float* tq    = (const float*)d_in[5];
    const float* tv    = (const float*)d_in[6];
    const float* wih   = (const float*)d_in[7];
    const float* whh   = (const float*)d_in[8];
    const float* bih   = (const float*)d_in[9];
    const float* bhh   = (const float*)d_in[10];
    const float* w1    = (const float*)d_in[11];
    const float* b1    = (const float*)d_in[12];
    const float* w2    = (const float*)d_in[13];
    const float* b2    = (const float*)d_in[14];
    const float* ling  = (const float*)d_in[15];
    const float* linb  = (const float*)d_in[16];
    const float* lslg  = (const float*)d_in[17];
    const float* lslb  = (const float*)d_in[18];
    const float* lffg  = (const float*)d_in[19];
    const float* lffb  = (const float*)d_in[20];
    const float* nzi   = (const float*)d_in[21];
    const float* nzf   = (const float*)d_in[22];

    float* out_slots = (float*)d_out;                  // [B,K,D]
    float* out_attn  = (float*)d_out + BB * KK * DD;   // [B,K,N,H]

    k_init_pre<<<BB * KK, 64>>>(mu, ls, mix0, nzi, tq, lslg, lslb);
    k_ln<<<BB * NN / 8, 256>>>(emb, ling, linb);
    k_keys<<<BB * 32, 256>>>(tk);
    for (int it = 0; it < 3; it++) {
        int last = (it == 2);
        k_pass<<<BB * 32, 256>>>(out_attn, last);
        k_upd<<<BB * KK, 128>>>(tk, tv, wih, whh, bih, bhh, w1, b1, w2, b2,
                                lffg, lffb, tq, lslg, lslb, nzf, out_slots, last);
    }
}

// round 4
// speedup vs baseline: 1.3255x; 1.0854x over previous
#include <cuda_runtime.h>
#include <math.h>

#define BB 16
#define NN 4096
#define DD 64
#define KK 8
#define HH 4
#define EPSF 1e-5f
// 16 * (-0.5 * 64 * ln(2*pi))
#define LOGPI_SUM (-940.99305800158484f)

typedef unsigned long long ull;

// ---------------- packed f32x2 helpers --------------------------------------
__device__ __forceinline__ ull pk2(float x, float y) {
    ull r; asm("mov.b64 %0, {%1, %2};" : "=l"(r) : "f"(x), "f"(y)); return r;
}
__device__ __forceinline__ void fma2(ull& d, ull a, ull b) {
    asm("fma.rn.f32x2 %0, %1, %2, %0;" : "+l"(d) : "l"(a), "l"(b));
}
__device__ __forceinline__ ull fma2r(ull a, ull b, ull c) {
    ull d; asm("fma.rn.f32x2 %0, %1, %2, %3;" : "=l"(d) : "l"(a), "l"(b), "l"(c)); return d;
}
__device__ __forceinline__ ull mul2(ull a, ull b) {
    ull d; asm("mul.rn.f32x2 %0, %1, %2;" : "=l"(d) : "l"(a), "l"(b)); return d;
}
union F4U { float4 v; ull u[2]; float s[4]; };

// ---------------- scratch (static device memory) ---------------------------
__device__ float g_x[BB * NN * DD];
__device__ float g_keys[(size_t)BB * NN * KK * DD];    // [b][n][k][d]
__device__ float g_slots[BB * KK * DD];
__device__ float g_sigma[BB * KK * DD];
__device__ float g_a[BB * KK * DD];     // -0.5/(sigma^2+eps)
__device__ float g_bq[BB * KK * DD];    // q/(sigma^2+eps)
__device__ float g_C[BB * KK * HH];     // logit bias per (b,k,h)
__device__ float g_A[BB * KK * HH];     // sum attn
__device__ float g_S2[BB * KK * DD];    // sum attn*k^2
__device__ float g_T[BB * KK * HH * DD];// sum attn*x  [b][k][h][e]

// ---------------- init + first-iteration coefficients ----------------------
__global__ void k_init_pre(const float* __restrict__ mu, const float* __restrict__ ls,
                           const float* __restrict__ mix0, const float* __restrict__ noise,
                           const float* __restrict__ tq, const float* __restrict__ gsl,
                           const float* __restrict__ bsl) {
    int bk = blockIdx.x, k = bk & (KK - 1);
    int d = threadIdx.x, h = d >> 4;
    __shared__ float sh[64];
    float sg = expf(ls[k * 64 + d]);
    float slot = mu[k * 64 + d] + sg * noise[bk * 64 + d];
    g_sigma[bk * 64 + d] = sg;
    g_slots[bk * 64 + d] = slot;
    sh[d] = slot;
    __syncthreads();
    float m = 0.f, q = 0.f;
#pragma unroll
    for (int j = 0; j < 64; j++) { float v = sh[j]; m += v; q += v * v; }
    m *= (1.f / 64.f);
    float var = q * (1.f / 64.f) - m * m;
    float sln = (slot - m) * rsqrtf(var + EPSF) * gsl[d] + bsl[d];
    float qd = sln * tq[((size_t)k * 64 + d) * 64 + d];
    float invden = 1.f / (sg * sg + EPSF);
    g_a[bk * 64 + d] = -0.5f * invden;
    g_bq[bk * 64 + d] = qd * invden;
    float cp = -logf(fmaxf(sg, EPSF)) - 0.5f * qd * qd * invden;
#pragma unroll
    for (int o = 1; o < 16; o <<= 1) cp += __shfl_xor_sync(0xffffffffu, cp, o);
    if ((d & 15) == 0) g_C[bk * 4 + h] = logf(mix0[k] + EPSF) + LOGPI_SUM + cp;
    g_S2[bk * 64 + d] = 0.f;
    if (d < 4) g_A[bk * 4 + d] = 0.f;
#pragma unroll
    for (int i = 0; i < 4; i++) g_T[bk * 256 + i * 64 + d] = 0.f;
}

// ---------------- LayerNorm of embeddings (warp per row) -------------------
__global__ void k_ln(const float* __restrict__ emb, const float* __restrict__ g,
                     const float* __restrict__ bt) {
    int row = blockIdx.x * 8 + (threadIdx.x >> 5);
    int lane = threadIdx.x & 31;
    float2 v = ((const float2*)emb)[(size_t)row * 32 + lane];
    float s = v.x + v.y, q = v.x * v.x + v.y * v.y;
#pragma unroll
    for (int o = 16; o; o >>= 1) {
        s += __shfl_xor_sync(0xffffffffu, s, o);
        q += __shfl_xor_sync(0xffffffffu, q, o);
    }
    float m = s * (1.f / 64.f);
    float var = q * (1.f / 64.f) - m * m;
    float r = rsqrtf(var + EPSF);
    float2 o;
    o.x = (v.x - m) * r * g[2 * lane] + bt[2 * lane];
    o.y = (v.y - m) * r * g[2 * lane + 1] + bt[2 * lane + 1];
    ((float2*)g_x)[(size_t)row * 32 + lane] = o;
}

// ---------------- keys GEMM: one (b, ntile, k) per block --------------------
__global__ __launch_bounds__(256, 2) void k_keys(const float* __restrict__ tk) {
    __shared__ float xs[128 * 64];   // [n][e]  32 KB
    __shared__ float ws[64 * 64];    // [e][d]  16 KB
    int bx = blockIdx.x;
    int k = bx & 7;
    int nt = (bx >> 3) & 31;
    int b = bx >> 8;
    int n0 = nt << 7;
    int t = threadIdx.x;
    const float4* xg = (const float4*)(g_x + ((size_t)b * NN + n0) * 64);
#pragma unroll
    for (int r = 0; r < 8; r++)
        ((float4*)xs)[t + r * 256] = xg[t + r * 256];
    const float4* wg = (const float4*)(tk + (size_t)k * 4096);
#pragma unroll
    for (int r = 0; r < 4; r++)
        ((float4*)ws)[t + r * 256] = wg[t + r * 256];
    __syncthreads();
    int tx = t & 7, ty = t >> 3;
    int d0 = tx << 3, nr = ty << 2;
    ull acc[4][4];
#pragma unroll
    for (int n = 0; n < 4; n++)
#pragma unroll
        for (int p = 0; p < 4; p++) acc[n][p] = 0ull;
#pragma unroll 8
    for (int e = 0; e < 64; e++) {
        F4U w0; w0.v = *(const float4*)&ws[e * 64 + d0];
        F4U w1; w1.v = *(const float4*)&ws[e * 64 + d0 + 4];
        float x0 = xs[(nr + 0) * 64 + e];
        float x1 = xs[(nr + 1) * 64 + e];
        float x2 = xs[(nr + 2) * 64 + e];
        float x3 = xs[(nr + 3) * 64 + e];
        ull xb0 = pk2(x0, x0);
        ull xb1 = pk2(x1, x1);
        ull xb2 = pk2(x2, x2);
        ull xb3 = pk2(x3, x3);
        fma2(acc[0][0], xb0, w0.u[0]); fma2(acc[0][1], xb0, w0.u[1]);
        fma2(acc[0][2], xb0, w1.u[0]); fma2(acc[0][3], xb0, w1.u[1]);
        fma2(acc[1][0], xb1, w0.u[0]); fma2(acc[1][1], xb1, w0.u[1]);
        fma2(acc[1][2], xb1, w1.u[0]); fma2(acc[1][3], xb1, w1.u[1]);
        fma2(acc[2][0], xb2, w0.u[0]); fma2(acc[2][1], xb2, w0.u[1]);
        fma2(acc[2][2], xb2, w1.u[0]); fma2(acc[2][3], xb2, w1.u[1]);
        fma2(acc[3][0], xb3, w0.u[0]); fma2(acc[3][1], xb3, w0.u[1]);
        fma2(acc[3][2], xb3, w1.u[0]); fma2(acc[3][3], xb3, w1.u[1]);
    }
    size_t o0 = (((size_t)b * NN + n0 + nr) * KK + k) * 64 + d0;
#pragma unroll
    for (int n = 0; n < 4; n++) {
        F4U oa, ob;
        oa.u[0] = acc[n][0]; oa.u[1] = acc[n][1];
        ob.u[0] = acc[n][2]; ob.u[1] = acc[n][3];
        *(float4*)&g_keys[o0 + (size_t)n * 512]     = oa.v;
        *(float4*)&g_keys[o0 + (size_t)n * 512 + 4] = ob.v;
    }
}

// ---------------- fused attention pass (two-phase, low-reg) -----------------
__global__ __launch_bounds__(256, 2) void k_pass(float* __restrict__ attn_out, int last) {
    __shared__ float4 xs[2048];       // [n][e/4]  32 KB
    __shared__ float attn_s[4096];    // [n][kh]   16 KB (reused as reduction scratch)
    int b = blockIdx.x >> 5;
    int n0 = (blockIdx.x & 31) << 7;
    int t = threadIdx.x, w = t >> 5, lane = t & 31;
    int bk = b * KK + (lane >> 2);
    int h = lane & 3;
    F4U a4[4], b4[4];
#pragma unroll
    for (int i = 0; i < 4; i++) {
        a4[i].v = *(const float4*)&g_a[bk * 64 + h * 16 + i * 4];
        b4[i].v = *(const float4*)&g_bq[bk * 64 + h * 16 + i * 4];
    }
    float C = g_C[bk * 4 + h];
    for (int i = t; i < 2048; i += 256)
        xs[i] = ((const float4*)g_x)[((size_t)b * NN + n0) * 16 + i];
    __syncthreads();

    F4U S2a[4];
#pragma unroll
    for (int j = 0; j < 4; j++) { S2a[j].u[0] = 0ull; S2a[j].u[1] = 0ull; }
    float Aacc = 0.f;
    float* aout = attn_out + (size_t)bk * NN * 4 + h;
    const float4* kbase = ((const float4*)g_keys) + ((size_t)b * NN + n0) * 128 + lane * 4;

    F4U q0, q1, q2, q3;
    { const float4* kp = kbase + (size_t)(w * 16) * 128;
      q0.v = kp[0]; q1.v = kp[1]; q2.v = kp[2]; q3.v = kp[3]; }
#pragma unroll 2
    for (int ni = 0; ni < 16; ni++) {
        int nl = w * 16 + ni;
        ull kp8[8] = {q0.u[0], q0.u[1], q1.u[0], q1.u[1], q2.u[0], q2.u[1], q3.u[0], q3.u[1]};
        if (ni < 15) {
            const float4* kp = kbase + (size_t)(nl + 1) * 128;
            q0.v = kp[0]; q1.v = kp[1]; q2.v = kp[2]; q3.v = kp[3];
        }
        ull lgp = 0ull;
#pragma unroll
        for (int j = 0; j < 8; j++) {
            ull tmp = fma2r(kp8[j], a4[j >> 1].u[j & 1], b4[j >> 1].u[j & 1]);
            lgp = fma2r(kp8[j], tmp, lgp);
        }
        F4U lgu; lgu.u[0] = lgp;
        float lg = C + lgu.s[0] + lgu.s[1];
        float mm = lg;
        mm = fmaxf(mm, __shfl_xor_sync(0xffffffffu, mm, 4));
        mm = fmaxf(mm, __shfl_xor_sync(0xffffffffu, mm, 8));
        mm = fmaxf(mm, __shfl_xor_sync(0xffffffffu, mm, 16));
        float ex = __expf(lg - mm);
        float ss = ex;
        ss += __shfl_xor_sync(0xffffffffu, ss, 4);
        ss += __shfl_xor_sync(0xffffffffu, ss, 8);
        ss += __shfl_xor_sync(0xffffffffu, ss, 16);
        float attn = __fdividef(ex, ss) + EPSF;
        attn_s[nl * 32 + lane] = attn;
        if (last) aout[(size_t)(n0 + nl) * 4] = attn;
        Aacc += attn;
        ull attn2 = pk2(attn, attn);
#pragma unroll
        for (int j = 0; j < 8; j++) {
            ull ak = mul2(attn2, kp8[j]);
            S2a[j >> 1].u[j & 1] = fma2r(ak, kp8[j], S2a[j >> 1].u[j & 1]);
        }
    }
    __syncthreads();

    // ---- phase 2: T[kh][e0..e0+7] = sum_n attn[n][kh] * x[n][e] -------------
    {
        int kh = t >> 3, et = t & 7;
        ull Tl[4] = {0ull, 0ull, 0ull, 0ull};
        const float* ap = attn_s + kh;
        const float4* xp = xs + et * 2;
#pragma unroll 4
        for (int n = 0; n < 128; n++) {
            float at = ap[n * 32];
            ull at2 = pk2(at, at);
            F4U xa; xa.v = xp[n * 16];
            F4U xb; xb.v = xp[n * 16 + 1];
            Tl[0] = fma2r(at2, xa.u[0], Tl[0]);
            Tl[1] = fma2r(at2, xa.u[1], Tl[1]);
            Tl[2] = fma2r(at2, xb.u[0], Tl[2]);
            Tl[3] = fma2r(at2, xb.u[1], Tl[3]);
        }
        int k2 = kh >> 2, h2 = kh & 3;
        float* gp = &g_T[(size_t)(b * KK + k2) * 256 + h2 * 64 + et * 8];
        F4U o0, o1;
        o0.u[0] = Tl[0]; o0.u[1] = Tl[1];
        o1.u[0] = Tl[2]; o1.u[1] = Tl[3];
#pragma unroll
        for (int j = 0; j < 4; j++) atomicAdd(gp + j, o0.s[j]);
#pragma unroll
        for (int j = 0; j < 4; j++) atomicAdd(gp + 4 + j, o1.s[j]);
    }

    // ---- S2 + A tree (reuse attn_s as scratch) ------------------------------
    __syncthreads();
    float* redf = attn_s;
#define SIDX(ww, j) ((ww) * 544 + lane * 17 + (j))
    if (w >= 4) {
#pragma unroll
        for (int j = 0; j < 16; j++) redf[SIDX(w - 4, j)] = S2a[j >> 2].s[j & 3];
        redf[SIDX(w - 4, 16)] = Aacc;
    }
    __syncthreads();
    if (w < 4) {
#pragma unroll
        for (int j = 0; j < 16; j++) S2a[j >> 2].s[j & 3] += redf[SIDX(w, j)];
        Aacc += redf[SIDX(w, 16)];
    }
    __syncthreads();
    if (w == 2 || w == 3) {
#pragma unroll
        for (int j = 0; j < 16; j++) redf[SIDX(w - 2, j)] = S2a[j >> 2].s[j & 3];
        redf[SIDX(w - 2, 16)] = Aacc;
    }
    __syncthreads();
    if (w < 2) {
#pragma unroll
        for (int j = 0; j < 16; j++) S2a[j >> 2].s[j & 3] += redf[SIDX(w, j)];
        Aacc += redf[SIDX(w, 16)];
    }
    __syncthreads();
    if (w == 1) {
#pragma unroll
        for (int j = 0; j < 16; j++) redf[SIDX(0, j)] = S2a[j >> 2].s[j & 3];
        redf[SIDX(0, 16)] = Aacc;
    }
    __syncthreads();
    if (w == 0) {
#pragma unroll
        for (int j = 0; j < 16; j++)
            atomicAdd(&g_S2[(size_t)b * 512 + lane * 16 + j],
                      S2a[j >> 2].s[j & 3] + redf[SIDX(0, j)]);
        atomicAdd(&g_A[b * 32 + lane], Aacc + redf[SIDX(0, 16)]);
    }
}

// ---------------- slot update + fused next-iter pre (128 threads) ----------
__global__ __launch_bounds__(128) void k_upd(
        const float* __restrict__ tk, const float* __restrict__ tv,
        const float* __restrict__ wih, const float* __restrict__ whh,
        const float* __restrict__ bih, const float* __restrict__ bhh,
        const float* __restrict__ w1, const float* __restrict__ b1,
        const float* __restrict__ w2, const float* __restrict__ b2,
        const float* __restrict__ gff, const float* __restrict__ bff,
        const float* __restrict__ tq, const float* __restrict__ gsl,
        const float* __restrict__ bsl,
        const float* __restrict__ noisef, float* __restrict__ out_slots, int last) {
    int bk = blockIdx.x;
    int k = bk & (KK - 1);
    int t = threadIdx.x;
    int d = t & 63, half = t >> 6;
    int h = d >> 4;
    __shared__ float Tsh[4][64], Ash[4];
    __shared__ float pu[2][64], ps1[2][64];
    __shared__ float ush[64], hsh[64];
    __shared__ float gsh[6][64];
    __shared__ float sh[64], presh[64], h1sh[256], pw2[2][64], osh[64];
    for (int i = t; i < 256; i += 128) Tsh[i >> 6][i & 63] = g_T[bk * 256 + i];
    if (t < 4) Ash[t] = g_A[bk * 4 + t];
    if (t >= 64) hsh[d] = g_slots[bk * 64 + d];
    __syncthreads();
    float Nk = Ash[0] + Ash[1] + Ash[2] + Ash[3];
    {
        float u = 0.f, s1 = 0.f;
        int e0 = half * 32;
#pragma unroll 8
        for (int e = e0; e < e0 + 32; e++) {
            float tvv = Tsh[h][e];
            u  = fmaf(tvv, tv[((size_t)k * 64 + e) * 64 + d], u);
            s1 = fmaf(tvv, tk[((size_t)k * 64 + e) * 64 + d], s1);
        }
        pu[half][d] = u; ps1[half][d] = s1;
    }
    __syncthreads();
    float sigma_d = 0.f, u = 0.f;
    if (t < 64) {
        u = pu[0][d] + pu[1][d];
        float s1 = ps1[0][d] + ps1[1][d];
        float invNk = 1.f / Nk;
        u *= (invNk + EPSF);                   // upd == nq
        float sig2 = fmaxf(g_S2[bk * 64 + d] - 2.f * u * s1 + u * u * Ash[h], 0.f);
        sigma_d = sqrtf(sig2 * invNk) + EPSF;
        g_sigma[bk * 64 + d] = sigma_d;
        ush[d] = u;
    }
    __syncthreads();
    {
        const float* W  = half ? whh : wih;
        const float* bi = half ? bhh : bih;
        const float* vi = half ? hsh : ush;
        float g0 = bi[d], g1 = bi[64 + d], g2 = bi[128 + d];
#pragma unroll 8
        for (int e = 0; e < 64; e++) {
            float v = vi[e];
            g0 = fmaf(v, W[d * 64 + e], g0);
            g1 = fmaf(v, W[(64 + d) * 64 + e], g1);
            g2 = fmaf(v, W[(128 + d) * 64 + e], g2);
        }
        gsh[half * 3 + 0][d] = g0;
        gsh[half * 3 + 1][d] = g1;
        gsh[half * 3 + 2][d] = g2;
    }
    __syncthreads();
    float snew = 0.f;
    if (t < 64) {
        float r = 1.f / (1.f + expf(-(gsh[0][d] + gsh[3][d])));
        float z = 1.f / (1.f + expf(-(gsh[1][d] + gsh[4][d])));
        float nn2 = tanhf(gsh[2][d] + r * gsh[5][d]);
        snew = (1.f - z) * nn2 + z * hsh[d];
        sh[d] = snew;
    }
    __syncthreads();
    if (t < 64) {
        float m = 0.f, qq = 0.f;
#pragma unroll
        for (int j = 0; j < 64; j++) { float v = sh[j]; m += v; qq += v * v; }
        m *= (1.f / 64.f);
        float var = qq * (1.f / 64.f) - m * m;
        presh[d] = (snew - m) * rsqrtf(var + EPSF) * gff[d] + bff[d];
    }
    __syncthreads();
    for (int j = t; j < 256; j += 128) {
        float acc = b1[j];
#pragma unroll 8
        for (int e = 0; e < 64; e++) acc = fmaf(presh[e], w1[(size_t)j * 64 + e], acc);
        h1sh[j] = fmaxf(acc, 0.f);
    }
    __syncthreads();
    {
        float o = 0.f;
        int j0 = half * 128;
#pragma unroll 8
        for (int j = j0; j < j0 + 128; j++) o = fmaf(h1sh[j], w2[(size_t)d * 256 + j], o);
        pw2[half][d] = o;
    }
    __syncthreads();
    if (t < 64) {
        float o = sh[d] + b2[d] + pw2[0][d] + pw2[1][d];
        g_slots[bk * 64 + d] = o;
        if (last) out_slots[bk * 64 + d] = o + sigma_d * noisef[bk * 64 + d];
        osh[d] = o;
    }
    __syncthreads();
    if (!last) {
        if (t < 64) {
            float m = 0.f, qq = 0.f;
#pragma unroll
            for (int j = 0; j < 64; j++) { float v = osh[j]; m += v; qq += v * v; }
            m *= (1.f / 64.f);
            float var = qq * (1.f / 64.f) - m * m;
            float sln = (osh[d] - m) * rsqrtf(var + EPSF) * gsl[d] + bsl[d];
            float qd = sln * tq[((size_t)k * 64 + d) * 64 + d];
            float invden = 1.f / (sigma_d * sigma_d + EPSF);
            g_a[bk * 64 + d]  = -0.5f * invden;
            g_bq[bk * 64 + d] = qd * invden;
            float cp = -logf(fmaxf(sigma_d, EPSF)) - 0.5f * qd * qd * invden;
#pragma unroll
            for (int o = 1; o < 16; o <<= 1) cp += __shfl_xor_sync(0xffffffffu, cp, o);
            if ((d & 15) == 0)
                g_C[bk * 4 + h] = logf(Nk * (1.f / (float)NN) + EPSF) + LOGPI_SUM + cp;
            g_S2[bk * 64 + d] = 0.f;
            if (d < 4) g_A[bk * 4 + d] = 0.f;
        }
        for (int i = t; i < 256; i += 128) g_T[bk * 256 + i] = 0.f;
    }
}

// ---------------- launch ----------------------------------------------------
extern "C" void kernel_launch(void* const* d_in, const int* in_sizes, int n_in,
                              void* d_out, int out_size) {
    const float* emb   = (const float*)d_in[0];
    const float* mu    = (const float*)d_in[1];
    const float* ls    = (const float*)d_in[2];
    const float* mix0  = (const float*)d_in[3];
    const float* tk    = (const float*)d_in[4];
    const float* tq    = (const float*)d_in[5];
    const float* tv    = (const float*)d_in[6];
    const float* wih   = (const float*)d_in[7];
    const float* whh   = (const float*)d_in[8];
    const float* bih   = (const float*)d_in[9];
    const float* bhh   = (const float*)d_in[10];
    const float* w1    = (const float*)d_in[11];
    const float* b1    = (const float*)d_in[12];
    const float* w2    = (const float*)d_in[13];
    const float* b2    = (const float*)d_in[14];
    const float* ling  = (const float*)d_in[15];
    const float* linb  = (const float*)d_in[16];
    const float* lslg  = (const float*)d_in[17];
    const float* lslb  = (const float*)d_in[18];
    const float* lffg  = (const float*)d_in[19];
    const float* lffb  = (const float*)d_in[20];
    const float* nzi   = (const float*)d_in[21];
    const float* nzf   = (const float*)d_in[22];

    float* out_slots = (float*)d_out;                  // [B,K,D]
    float* out_attn  = (float*)d_out + BB * KK * DD;   // [B,K,N,H]

    k_init_pre<<<BB * KK, 64>>>(mu, ls, mix0, nzi, tq, lslg, lslb);
    k_ln<<<BB * NN / 8, 256>>>(emb, ling, linb);
    k_keys<<<BB * 32 * KK, 256>>>(tk);
    for (int it = 0; it < 3; it++) {
        int last = (it == 2);
        k_pass<<<BB * 32, 256>>>(out_attn, last);
        k_upd<<<BB * KK, 128>>>(tk, tv, wih, whh, bih, bhh, w1, b1, w2, b2,
                                lffg, lffb, tq, lslg, lslb, nzf, out_slots, last);
    }
}